// round 3
// baseline (speedup 1.0000x reference)
#include <cuda_runtime.h>
#include <cstdint>

// Voxelization: per-point voxel coords.
//   input : points [N, 4] float32 (x, y, z, feat)
//   output: [3, N] float32 (harness transports int32 reference as f32),
//           rows = (z, y, x); -1.0f everywhere for out-of-range points.
//
// Constants (must match the reference exactly, as fp32):
//   voxel_size = (0.05, 0.05, 0.1)
//   pc_range mins = (0.0, -40.0, -3.0)
//   grid = (1408, 1600, 40)

#define VSX 0.05f
#define VSY 0.05f
#define VSZ 0.1f
#define MINX 0.0f
#define MINY -40.0f
#define MINZ -3.0f
#define GXF 1408.0f
#define GYF 1600.0f
#define GZF 40.0f

__device__ __forceinline__ void voxel_coord(const float4 p, float& cx, float& cy, float& cz) {
    // IEEE round-to-nearest division to exactly match the fp32 reference
    // (0.05f is not exactly representable; mul-by-20 would flip boundary voxels).
    const float fx = floorf(__fdiv_rn(p.x - MINX, VSX));
    const float fy = floorf(__fdiv_rn(p.y - MINY, VSY));
    const float fz = floorf(__fdiv_rn(p.z - MINZ, VSZ));
    // floor results are integral; compare in float (all grid bounds exact in f32).
    const bool valid = (fx >= 0.0f) & (fx < GXF) &
                       (fy >= 0.0f) & (fy < GYF) &
                       (fz >= 0.0f) & (fz < GZF);
    cx = valid ? fx : -1.0f;
    cy = valid ? fy : -1.0f;
    cz = valid ? fz : -1.0f;
}

__global__ __launch_bounds__(256)
void voxelize_kernel(const float4* __restrict__ pts,
                     float* __restrict__ out,   // [3, N]: z row, y row, x row
                     int n) {
    const long long g = (long long)blockIdx.x * blockDim.x + threadIdx.x;
    const long long base = g << 2;   // 4 points per thread
    if (base >= n) return;

    float* __restrict__ out_z = out;
    float* __restrict__ out_y = out + n;
    float* __restrict__ out_x = out + 2LL * n;

    if (base + 3 < n) {
        // Vector path: 4 x LDG.128 in, 3 x STG.128 out.
        const float4 p0 = pts[base + 0];
        const float4 p1 = pts[base + 1];
        const float4 p2 = pts[base + 2];
        const float4 p3 = pts[base + 3];

        float4 vz, vy, vx;
        voxel_coord(p0, vx.x, vy.x, vz.x);
        voxel_coord(p1, vx.y, vy.y, vz.y);
        voxel_coord(p2, vx.z, vy.z, vz.z);
        voxel_coord(p3, vx.w, vy.w, vz.w);

        *reinterpret_cast<float4*>(out_z + base) = vz;
        *reinterpret_cast<float4*>(out_y + base) = vy;
        *reinterpret_cast<float4*>(out_x + base) = vx;
    } else {
        // Scalar tail (only hit if n % 4 != 0).
        for (long long i = base; i < n; ++i) {
            const float4 p = pts[i];
            float cx, cy, cz;
            voxel_coord(p, cx, cy, cz);
            out_z[i] = cz;
            out_y[i] = cy;
            out_x[i] = cx;
        }
    }
}

extern "C" void kernel_launch(void* const* d_in, const int* in_sizes, int n_in,
                              void* d_out, int out_size) {
    const float4* pts = (const float4*)d_in[0];
    float* out = (float*)d_out;
    const int n = in_sizes[0] / 4;   // points are [N, 4] floats

    const int n_groups = (n + 3) / 4;          // 4 points per thread
    const int threads = 256;
    const int blocks = (n_groups + threads - 1) / threads;
    voxelize_kernel<<<blocks, threads>>>(pts, out, n);
}